// round 2
// baseline (speedup 1.0000x reference)
#include <cuda_runtime.h>
#include <cuda_bf16.h>
#include <math_constants.h>
#include <cstdint>

// ---------------------------------------------------------------------------
// Problem constants (fixed by setup_inputs)
// ---------------------------------------------------------------------------
#define BB 8
#define NN 4096
#define KNBR 20
#define DIMG 1024

// ---------------------------------------------------------------------------
// Scratch (device globals; no allocations allowed)
// ---------------------------------------------------------------------------
__device__ float    d_xt  [BB * NN * 3];
__device__ float    d_cat [BB * NN * 192];    // [x1 | x2 | x3] slices
__device__ int      d_idx [BB * NN * KNBR];
__device__ unsigned d_gu  [BB * DIMG];
__device__ float    d_gdot[BB * 256];
__device__ float    d_h8  [BB * NN * 256];
__device__ float    d_h9  [BB * NN * 256];
__device__ float    d_h10 [BB * NN * 128];

// ---------------------------------------------------------------------------
// Helpers
// ---------------------------------------------------------------------------
__device__ __forceinline__ float lrelu(float y) { return y > 0.f ? y : 0.2f * y; }

// monotone float->uint encoding so atomicMax(unsigned) == float max
__device__ __forceinline__ unsigned encf(float v) {
    unsigned u = __float_as_uint(v);
    return (u & 0x80000000u) ? ~u : (u | 0x80000000u);
}
__device__ __forceinline__ float decf(unsigned u) {
    return __uint_as_float((u & 0x80000000u) ? (u & 0x7fffffffu) : ~u);
}

// ---------------------------------------------------------------------------
// Transpose x (B,3,N) -> xt (B,N,3)
// ---------------------------------------------------------------------------
__global__ void xt_kernel(const float* __restrict__ x, float* __restrict__ xt) {
    int gp = blockIdx.x * blockDim.x + threadIdx.x;   // 0..B*N
    if (gp >= BB * NN) return;
    int b = gp >> 12;
    int n = gp & (NN - 1);
#pragma unroll
    for (int c = 0; c < 3; c++)
        xt[gp * 3 + c] = x[((size_t)b * 3 + c) * NN + n];
}

// ---------------------------------------------------------------------------
// KNN, C=3 : thread per row, shared tile of candidates
// pd = 2*dot - ||xi||^2 - ||xj||^2 ; keep top-20 largest pd (stable ties)
// ---------------------------------------------------------------------------
__global__ __launch_bounds__(128) void knn3_kernel(
    const float* __restrict__ feat, int stride, int* __restrict__ idxo)
{
    const int TT = 64;
    int b = blockIdx.y;
    int n = blockIdx.x * blockDim.x + threadIdx.x;
    const float* base = feat + (size_t)b * NN * stride;

    float f0 = base[(size_t)n * stride + 0];
    float f1 = base[(size_t)n * stride + 1];
    float f2 = base[(size_t)n * stride + 2];
    float my2 = f0 * f0 + f1 * f1 + f2 * f2;

    float topv[KNBR]; int topi[KNBR];
#pragma unroll
    for (int i = 0; i < KNBR; i++) { topv[i] = -CUDART_INF_F; topi[i] = 0; }
    float thr = -CUDART_INF_F;

    __shared__ float tile[TT * 3];
    __shared__ float txx[TT];

    for (int m0 = 0; m0 < NN; m0 += TT) {
        __syncthreads();
        for (int e = threadIdx.x; e < TT * 3; e += blockDim.x) {
            int j = e / 3, c = e % 3;
            tile[e] = base[(size_t)(m0 + j) * stride + c];
        }
        __syncthreads();
        if (threadIdx.x < TT) {
            float a = tile[threadIdx.x * 3 + 0];
            float bq = tile[threadIdx.x * 3 + 1];
            float cq = tile[threadIdx.x * 3 + 2];
            txx[threadIdx.x] = a * a + bq * bq + cq * cq;
        }
        __syncthreads();
#pragma unroll 4
        for (int j = 0; j < TT; j++) {
            float dot = f0 * tile[j * 3 + 0] + f1 * tile[j * 3 + 1] + f2 * tile[j * 3 + 2];
            float v = 2.0f * dot - my2 - txx[j];
            if (v > thr) {
                int p = KNBR - 1;
#pragma unroll 1
                while (p > 0 && v > topv[p - 1]) {
                    topv[p] = topv[p - 1]; topi[p] = topi[p - 1]; p--;
                }
                topv[p] = v; topi[p] = m0 + j;
                thr = topv[KNBR - 1];
            }
        }
    }
    int* op = idxo + ((size_t)b * NN + n) * KNBR;
#pragma unroll
    for (int i = 0; i < KNBR; i++) op[i] = topi[i];
}

// ---------------------------------------------------------------------------
// KNN, C=64 : float4 register query against shared tile
// ---------------------------------------------------------------------------
__global__ __launch_bounds__(128) void knn64_kernel(
    const float* __restrict__ feat, int stride, int* __restrict__ idxo)
{
    const int TT = 64;
    const int C = 64;
    int b = blockIdx.y;
    int n = blockIdx.x * blockDim.x + threadIdx.x;
    const float* base = feat + (size_t)b * NN * stride;

    float4 f4[16];
#pragma unroll
    for (int q = 0; q < 16; q++)
        f4[q] = *(const float4*)&base[(size_t)n * stride + q * 4];
    float my2 = 0.f;
#pragma unroll
    for (int q = 0; q < 16; q++)
        my2 += f4[q].x * f4[q].x + f4[q].y * f4[q].y + f4[q].z * f4[q].z + f4[q].w * f4[q].w;

    float topv[KNBR]; int topi[KNBR];
#pragma unroll
    for (int i = 0; i < KNBR; i++) { topv[i] = -CUDART_INF_F; topi[i] = 0; }
    float thr = -CUDART_INF_F;

    __shared__ float tile[TT * C];
    __shared__ float txx[TT];

    for (int m0 = 0; m0 < NN; m0 += TT) {
        __syncthreads();
        // vectorized tile load: 1024 float4s by 128 threads
        for (int e4 = threadIdx.x; e4 < TT * C / 4; e4 += blockDim.x) {
            int j = e4 >> 4, q = e4 & 15;
            *(float4*)&tile[j * C + q * 4] =
                *(const float4*)&base[(size_t)(m0 + j) * stride + q * 4];
        }
        __syncthreads();
        if (threadIdx.x < TT) {
            float s2 = 0.f;
#pragma unroll
            for (int c = 0; c < C; c++) { float t = tile[threadIdx.x * C + c]; s2 += t * t; }
            txx[threadIdx.x] = s2;
        }
        __syncthreads();
#pragma unroll 2
        for (int j = 0; j < TT; j++) {
            const float4* trow = (const float4*)&tile[j * C];
            float dot = 0.f;
#pragma unroll
            for (int q = 0; q < 16; q++) {
                float4 t = trow[q];
                dot += f4[q].x * t.x + f4[q].y * t.y + f4[q].z * t.z + f4[q].w * t.w;
            }
            float v = 2.0f * dot - my2 - txx[j];
            if (v > thr) {
                int p = KNBR - 1;
#pragma unroll 1
                while (p > 0 && v > topv[p - 1]) {
                    topv[p] = topv[p - 1]; topi[p] = topi[p - 1]; p--;
                }
                topv[p] = v; topi[p] = m0 + j;
                thr = topv[KNBR - 1];
            }
        }
    }
    int* op = idxo + ((size_t)b * NN + n) * KNBR;
#pragma unroll
    for (int i = 0; i < KNBR; i++) op[i] = topi[i];
}

// ---------------------------------------------------------------------------
// Edge-conv stage: gather -> [nbr-ctr, ctr] -> cbl1 (-> cbl2) -> max over k
// Warp processes G=4 points; weights in dynamic shared (padded, float4 LDS).
// Output goes to a 64-wide slice of d_cat (row stride 192).
// ---------------------------------------------------------------------------
template <int CIN, bool TWO>
__global__ __launch_bounds__(256) void stage_kernel(
    const float* __restrict__ in, int istride,
    const int* __restrict__ idx,
    const float* __restrict__ w1, const float* __restrict__ s1v, const float* __restrict__ b1v,
    const float* __restrict__ w2, const float* __restrict__ s2v, const float* __restrict__ b2v,
    float* __restrict__ out)
{
    constexpr int F  = 2 * CIN;
    constexpr int P1 = (F == 6) ? 8 : (F + 4);   // pad so 8-lane phases hit distinct banks
    constexpr int P2 = 68;
    constexpr int NW = 8, G = 4;

    extern __shared__ float sm[];
    float* w1sh = sm;                                    // 64*P1
    float* w2sh = w1sh + 64 * P1;                        // 64*P2 (if TWO)
    float* s1sh = w2sh + (TWO ? 64 * P2 : 0);
    float* b1sh = s1sh + 64;
    float* s2sh = b1sh + 64;
    float* b2sh = s2sh + 64;
    float* featb = b2sh + 64;                            // NW*G*F
    float* h1b   = featb + NW * G * F;                   // NW*G*64 (if TWO)

    int tid = threadIdx.x;
    for (int e = tid; e < 64 * F; e += NW * 32) { int o = e / F, c = e % F; w1sh[o * P1 + c] = w1[e]; }
    if constexpr (TWO)
        for (int e = tid; e < 64 * 64; e += NW * 32) { int o = e >> 6, c = e & 63; w2sh[o * P2 + c] = w2[e]; }
    if (tid < 64) {
        s1sh[tid] = s1v[tid]; b1sh[tid] = b1v[tid];
        if constexpr (TWO) { s2sh[tid] = s2v[tid]; b2sh[tid] = b2v[tid]; }
    }
    __syncthreads();

    int warp = tid >> 5, lane = tid & 31;
    int p0 = blockIdx.x * (NW * G) + warp * G;
    int rbase = (p0 / NN) * NN;  // batch row base (group never straddles batches)
    float* feat = featb + warp * (G * F);
    float* h1 = h1b + warp * (G * 64);

    // centers into feat[.., CIN..F)
#pragma unroll
    for (int g = 0; g < G; g++) {
        int gp = p0 + g;
        for (int c = lane; c < CIN; c += 32)
            feat[g * F + CIN + c] = in[(size_t)gp * istride + c];
    }

    float mx0[G], mx1[G];
#pragma unroll
    for (int g = 0; g < G; g++) { mx0[g] = -CUDART_INF_F; mx1[g] = -CUDART_INF_F; }

    float sA = s1sh[lane], bA = b1sh[lane], sB = s1sh[lane + 32], bB = b1sh[lane + 32];
    float s2A = 0, b2A = 0, s2B = 0, b2B = 0;
    if constexpr (TWO) { s2A = s2sh[lane]; b2A = b2sh[lane]; s2B = s2sh[lane + 32]; b2B = b2sh[lane + 32]; }

    for (int kk = 0; kk < KNBR; kk++) {
        __syncwarp();
#pragma unroll
        for (int g = 0; g < G; g++) {
            int j = idx[((size_t)(p0 + g)) * KNBR + kk];
            for (int c = lane; c < CIN; c += 32)
                feat[g * F + c] = in[(size_t)(rbase + j) * istride + c] - feat[g * F + CIN + c];
        }
        __syncwarp();

        // layer 1: lane computes outputs (lane) and (lane+32) for G points
        float a0[G], a1[G];
#pragma unroll
        for (int g = 0; g < G; g++) { a0[g] = 0.f; a1[g] = 0.f; }
        if constexpr (F == 6) {
#pragma unroll
            for (int c = 0; c < 6; c++) {
                float wv0 = w1sh[lane * P1 + c], wv1 = w1sh[(lane + 32) * P1 + c];
#pragma unroll
                for (int g = 0; g < G; g++) {
                    float fv = feat[g * F + c];
                    a0[g] += wv0 * fv; a1[g] += wv1 * fv;
                }
            }
        } else {
            const float4* wp0 = (const float4*)&w1sh[lane * P1];
            const float4* wp1 = (const float4*)&w1sh[(lane + 32) * P1];
#pragma unroll
            for (int q = 0; q < F / 4; q++) {
                float4 wa = wp0[q], wb = wp1[q];
#pragma unroll
                for (int g = 0; g < G; g++) {
                    float4 fv = ((const float4*)&feat[g * F])[q];
                    a0[g] += wa.x * fv.x + wa.y * fv.y + wa.z * fv.z + wa.w * fv.w;
                    a1[g] += wb.x * fv.x + wb.y * fv.y + wb.z * fv.z + wb.w * fv.w;
                }
            }
        }
#pragma unroll
        for (int g = 0; g < G; g++) {
            float y0 = lrelu(a0[g] * sA + bA);
            float y1 = lrelu(a1[g] * sB + bB);
            if constexpr (TWO) {
                h1[g * 64 + lane] = y0;
                h1[g * 64 + lane + 32] = y1;
            } else {
                mx0[g] = fmaxf(mx0[g], y0);
                mx1[g] = fmaxf(mx1[g], y1);
            }
        }
        if constexpr (TWO) {
            __syncwarp();
            float c0[G], c1[G];
#pragma unroll
            for (int g = 0; g < G; g++) { c0[g] = 0.f; c1[g] = 0.f; }
            const float4* vp0 = (const float4*)&w2sh[lane * P2];
            const float4* vp1 = (const float4*)&w2sh[(lane + 32) * P2];
#pragma unroll
            for (int q = 0; q < 16; q++) {
                float4 wa = vp0[q], wb = vp1[q];
#pragma unroll
                for (int g = 0; g < G; g++) {
                    float4 hv = ((const float4*)&h1[g * 64])[q];
                    c0[g] += wa.x * hv.x + wa.y * hv.y + wa.z * hv.z + wa.w * hv.w;
                    c1[g] += wb.x * hv.x + wb.y * hv.y + wb.z * hv.z + wb.w * hv.w;
                }
            }
#pragma unroll
            for (int g = 0; g < G; g++) {
                mx0[g] = fmaxf(mx0[g], lrelu(c0[g] * s2A + b2A));
                mx1[g] = fmaxf(mx1[g], lrelu(c1[g] * s2B + b2B));
            }
        }
    }
#pragma unroll
    for (int g = 0; g < G; g++) {
        out[(size_t)(p0 + g) * 192 + lane]      = mx0[g];
        out[(size_t)(p0 + g) * 192 + lane + 32] = mx1[g];
    }
}

// ---------------------------------------------------------------------------
// Tiled fp32 GEMM: Y[m,o] = sum_k A[m,k+woffA]*W[o*ldw + woff + k]
// 64x64 tile, 16-deep k, 256 threads, 4x4 per thread.
// MODE 0: row-major store (+scale/bias/leaky/extra)
// MODE 1: final transposed store out[b,o,n], guard o<13
// MODE 2: leaky then max over rows -> atomicMax into g (encoded)
// ---------------------------------------------------------------------------
template <int MODE, bool SB, bool EXT, bool LEAKY>
__global__ __launch_bounds__(256) void gemm_kernel(
    const float* __restrict__ A, int lda,
    const float* __restrict__ W, int ldw, int woff,
    const float* __restrict__ sv, const float* __restrict__ bv,
    const float* __restrict__ ext,
    float* __restrict__ outp, unsigned* __restrict__ gout,
    int Nout, int Ktot)
{
    __shared__ float As[16][68];
    __shared__ float Ws[16][68];

    int tid = threadIdx.x;
    int tx = tid & 15, ty = tid >> 4;
    int rowBase = blockIdx.y * 64, colBase = blockIdx.x * 64;
    int lr = tid >> 2, lk = tid & 3;

    float acc[4][4];
#pragma unroll
    for (int i = 0; i < 4; i++)
#pragma unroll
        for (int j = 0; j < 4; j++) acc[i][j] = 0.f;

    for (int k0 = 0; k0 < Ktot; k0 += 16) {
        float4 av = *(const float4*)&A[(size_t)(rowBase + lr) * lda + k0 + lk * 4];
        float4 wv = make_float4(0.f, 0.f, 0.f, 0.f);
        if (colBase + lr < Nout)
            wv = *(const float4*)&W[(size_t)(colBase + lr) * ldw + woff + k0 + lk * 4];
        __syncthreads();
        As[lk * 4 + 0][lr] = av.x; As[lk * 4 + 1][lr] = av.y;
        As[lk * 4 + 2][lr] = av.z; As[lk * 4 + 3][lr] = av.w;
        Ws[lk * 4 + 0][lr] = wv.x; Ws[lk * 4 + 1][lr] = wv.y;
        Ws[lk * 4 + 2][lr] = wv.z; Ws[lk * 4 + 3][lr] = wv.w;
        __syncthreads();
#pragma unroll
        for (int k = 0; k < 16; k++) {
            float4 a = *(const float4*)&As[k][ty * 4];
            float4 w = *(const float4*)&Ws[k][tx * 4];
            acc[0][0] += a.x * w.x; acc[0][1] += a.x * w.y; acc[0][2] += a.x * w.z; acc[0][3] += a.x * w.w;
            acc[1][0] += a.y * w.x; acc[1][1] += a.y * w.y; acc[1][2] += a.y * w.z; acc[1][3] += a.y * w.w;
            acc[2][0] += a.z * w.x; acc[2][1] += a.z * w.y; acc[2][2] += a.z * w.z; acc[2][3] += a.z * w.w;
            acc[3][0] += a.w * w.x; acc[3][1] += a.w * w.y; acc[3][2] += a.w * w.z; acc[3][3] += a.w * w.w;
        }
    }

    int bidx = rowBase >> 12;   // rowBase / 4096 (tiles never straddle batches)

    if (MODE == 2) {
#pragma unroll
        for (int j = 0; j < 4; j++) {
            int o = colBase + tx * 4 + j;
            float sc = SB ? sv[o] : 1.f;
            float bi = SB ? bv[o] : 0.f;
            float m = -CUDART_INF_F;
#pragma unroll
            for (int i = 0; i < 4; i++) {
                float v = acc[i][j];
                if (SB) v = v * sc + bi;
                if (LEAKY) v = lrelu(v);
                m = fmaxf(m, v);
            }
            atomicMax(&gout[bidx * DIMG + o], encf(m));
        }
    } else {
#pragma unroll
        for (int j = 0; j < 4; j++) {
            int o = colBase + tx * 4 + j;
            float sc = SB ? sv[o] : 1.f;
            float bi = SB ? bv[o] : 0.f;
            float ex = EXT ? ext[bidx * Nout + o] : 0.f;
#pragma unroll
            for (int i = 0; i < 4; i++) {
                int r = rowBase + ty * 4 + i;
                float v = acc[i][j];
                if (EXT) v += ex;
                if (SB) v = v * sc + bi;
                if (LEAKY) v = lrelu(v);
                if (MODE == 0) {
                    outp[(size_t)r * Nout + o] = v;
                } else {
                    if (o < 13)
                        outp[((size_t)bidx * 13 + o) * NN + (r & (NN - 1))] = v;
                }
            }
        }
    }
}

// ---------------------------------------------------------------------------
// g-buffer init + gdot = w8[:, :1024] @ g  (per batch)
// ---------------------------------------------------------------------------
__global__ void zero_gu_kernel(unsigned* __restrict__ gu) {
    int t = blockIdx.x * blockDim.x + threadIdx.x;
    if (t < BB * DIMG) gu[t] = 0u;
}

__global__ __launch_bounds__(256) void gdot_kernel(
    const unsigned* __restrict__ gu, const float* __restrict__ w8, float* __restrict__ gdot)
{
    int b = blockIdx.x;
    __shared__ float gsh[DIMG];
    for (int i = threadIdx.x; i < DIMG; i += blockDim.x) gsh[i] = decf(gu[b * DIMG + i]);
    __syncthreads();
    int warp = threadIdx.x >> 5, lane = threadIdx.x & 31;
    for (int o = warp * 32; o < warp * 32 + 32; o++) {
        float accv = 0.f;
        for (int c = lane; c < DIMG; c += 32)
            accv += w8[(size_t)o * 1216 + c] * gsh[c];
#pragma unroll
        for (int off = 16; off; off >>= 1)
            accv += __shfl_down_sync(0xffffffffu, accv, off);
        if (lane == 0) gdot[b * 256 + o] = accv;
    }
}

// ---------------------------------------------------------------------------
// Launcher
// ---------------------------------------------------------------------------
extern "C" void kernel_launch(void* const* d_in, const int* in_sizes, int n_in,
                              void* d_out, int out_size)
{
    (void)in_sizes; (void)n_in; (void)out_size;

    const float* x   = (const float*)d_in[0];
    const float* w1  = (const float*)d_in[1];
    const float* s1  = (const float*)d_in[2];
    const float* b1  = (const float*)d_in[3];
    const float* w2  = (const float*)d_in[4];
    const float* s2  = (const float*)d_in[5];
    const float* b2  = (const float*)d_in[6];
    const float* w3  = (const float*)d_in[7];
    const float* s3  = (const float*)d_in[8];
    const float* b3  = (const float*)d_in[9];
    const float* w4  = (const float*)d_in[10];
    const float* s4  = (const float*)d_in[11];
    const float* b4  = (const float*)d_in[12];
    const float* w5  = (const float*)d_in[13];
    const float* s5  = (const float*)d_in[14];
    const float* b5  = (const float*)d_in[15];
    const float* w6  = (const float*)d_in[16];
    const float* s6  = (const float*)d_in[17];
    const float* b6  = (const float*)d_in[18];
    const float* w8  = (const float*)d_in[19];
    const float* s8  = (const float*)d_in[20];
    const float* b8  = (const float*)d_in[21];
    const float* w9  = (const float*)d_in[22];
    const float* s9  = (const float*)d_in[23];
    const float* b9  = (const float*)d_in[24];
    const float* w10 = (const float*)d_in[25];
    const float* s10 = (const float*)d_in[26];
    const float* b10 = (const float*)d_in[27];
    const float* w11 = (const float*)d_in[28];
    float* out = (float*)d_out;

    void* p;
    cudaGetSymbolAddress(&p, d_xt);   float*    xt   = (float*)p;
    cudaGetSymbolAddress(&p, d_cat);  float*    cat  = (float*)p;
    cudaGetSymbolAddress(&p, d_idx);  int*      idx  = (int*)p;
    cudaGetSymbolAddress(&p, d_gu);   unsigned* gu   = (unsigned*)p;
    cudaGetSymbolAddress(&p, d_gdot); float*    gdot = (float*)p;
    cudaGetSymbolAddress(&p, d_h8);   float*    h8   = (float*)p;
    cudaGetSymbolAddress(&p, d_h9);   float*    h9   = (float*)p;
    cudaGetSymbolAddress(&p, d_h10);  float*    h10  = (float*)p;

    // dynamic smem sizes for stage kernels (must allow >48KB)
    const int sz1 = (64 * 8   + 64 * 68 + 256 + 8 * 4 * 6   + 8 * 4 * 64) * 4; // 29440
    const int sz2 = (64 * 132 + 64 * 68 + 256 + 8 * 4 * 128 + 8 * 4 * 64) * 4; // 76800
    const int sz3 = (64 * 132 +           256 + 8 * 4 * 128             ) * 4; // 51200
    cudaFuncSetAttribute((const void*)stage_kernel<3, true>,
                         cudaFuncAttributeMaxDynamicSharedMemorySize, sz1);
    cudaFuncSetAttribute((const void*)stage_kernel<64, true>,
                         cudaFuncAttributeMaxDynamicSharedMemorySize, sz2);
    cudaFuncSetAttribute((const void*)stage_kernel<64, false>,
                         cudaFuncAttributeMaxDynamicSharedMemorySize, sz3);

    const int PTS = BB * NN;                 // 32768
    dim3 knnGrid(NN / 128, BB);

    // 1) transpose
    xt_kernel<<<PTS / 256, 256>>>(x, xt);

    // 2) edge-conv block 1 (3 -> 64)
    knn3_kernel<<<knnGrid, 128>>>(xt, 3, idx);
    stage_kernel<3, true><<<PTS / 32, 256, sz1>>>(
        xt, 3, idx, w1, s1, b1, w2, s2, b2, cat + 0);

    // 3) edge-conv block 2 (64 -> 64)
    knn64_kernel<<<knnGrid, 128>>>(cat + 0, 192, idx);
    stage_kernel<64, true><<<PTS / 32, 256, sz2>>>(
        cat + 0, 192, idx, w3, s3, b3, w4, s4, b4, cat + 64);

    // 4) edge-conv block 3 (64 -> 64, single layer)
    knn64_kernel<<<knnGrid, 128>>>(cat + 64, 192, idx);
    stage_kernel<64, false><<<PTS / 32, 256, sz3>>>(
        cat + 64, 192, idx, w5, s5, b5, nullptr, nullptr, nullptr, cat + 128);

    // 5) cbl6 (192 -> 1024) fused with max-over-N via atomic max
    zero_gu_kernel<<<(BB * DIMG + 255) / 256, 256>>>(gu);
    gemm_kernel<2, true, false, true><<<dim3(DIMG / 64, PTS / 64), 256>>>(
        cat, 192, w6, 192, 0, s6, b6, nullptr, nullptr, gu, DIMG, 192);

    // 6) gdot[b,o] = w8[o, :1024] . g[b]
    gdot_kernel<<<BB, 256>>>(gu, w8, gdot);

    // 7) cbl8: (gdot + w8[:,1024:] @ cat) * s8 + b8, leaky
    gemm_kernel<0, true, true, true><<<dim3(256 / 64, PTS / 64), 256>>>(
        cat, 192, w8, 1216, 1024, s8, b8, gdot, h8, nullptr, 256, 192);

    // 8) cbl9
    gemm_kernel<0, true, false, true><<<dim3(256 / 64, PTS / 64), 256>>>(
        h8, 256, w9, 256, 0, s9, b9, nullptr, h9, nullptr, 256, 256);

    // 9) cbl10
    gemm_kernel<0, true, false, true><<<dim3(128 / 64, PTS / 64), 256>>>(
        h9, 256, w10, 256, 0, s10, b10, nullptr, h10, nullptr, 128, 256);

    // 10) classifier + transpose to (B,13,N)
    gemm_kernel<1, false, false, false><<<dim3(1, PTS / 64), 256>>>(
        h10, 128, w11, 128, 0, nullptr, nullptr, nullptr, out, nullptr, 13, 128);
}